// round 15
// baseline (speedup 1.0000x reference)
#include <cuda_runtime.h>
#include <cuda_bf16.h>
#include <cstdint>
#include <math.h>

#define MROWS 4096
#define DMODEL 1024
#define VOCAB 32000
#define DFF 2048
#define MD ((size_t)MROWS * DMODEL)

// ---------------- scratch (allocation-free rule) ----------------
__device__ float g_tmp[MD], g_x1[MD], g_x2[MD];
__device__ float g_rs[65536];
__device__ __nv_bfloat16 g_Pb[(size_t)MROWS * VOCAB];
__device__ __nv_bfloat16 g_eb[(size_t)VOCAB * DMODEL];
__device__ __nv_bfloat16 g_ebT[(size_t)VOCAB * DMODEL];
__device__ __nv_bfloat16 g_tgtb[MD], g_srcb[MD], g_avb[MD], g_x1b[MD], g_x2b[MD];
__device__ __nv_bfloat16 g_qb[MD], g_kb[MD], g_vtb[MD], g_yb[MD];
__device__ __nv_bfloat16 g_hb[(size_t)MROWS * DFF];
__device__ __nv_bfloat16 g_vawT[(size_t)2 * DMODEL * DMODEL];
__device__ __nv_bfloat16 g_wT[8][(size_t)DMODEL * DMODEL];
__device__ __nv_bfloat16 g_f1T[(size_t)DFF * DMODEL];
__device__ __nv_bfloat16 g_f2T[(size_t)DFF * DMODEL];

// ---------------- PTX helpers ----------------
__device__ __forceinline__ uint32_t smem_u32(const void* p) {
    uint32_t a;
    asm("{ .reg .u64 t; cvta.to.shared.u64 t, %1; cvt.u32.u64 %0, t; }" : "=r"(a) : "l"(p));
    return a;
}
#define CP_ASYNC16(dst, src) \
    asm volatile("cp.async.cg.shared.global [%0], [%1], 16;" \
                 :: "r"(dst), "l"(__cvta_generic_to_global(src)) : "memory")
#define CP_COMMIT() asm volatile("cp.async.commit_group;" ::: "memory")
#define LDSM4(r0, r1, r2, r3, a) \
    asm volatile("ldmatrix.sync.aligned.m8n8.x4.shared.b16 {%0,%1,%2,%3}, [%4];" \
                 : "=r"(r0), "=r"(r1), "=r"(r2), "=r"(r3) : "r"(a))
#define MMA16816(c, a, b) \
    asm volatile("mma.sync.aligned.m16n8k16.row.col.f32.bf16.bf16.f32 " \
                 "{%0,%1,%2,%3}, {%4,%5,%6,%7}, {%8,%9}, {%0,%1,%2,%3};" \
                 : "+f"((c)[0]), "+f"((c)[1]), "+f"((c)[2]), "+f"((c)[3]) \
                 : "r"((a)[0]), "r"((a)[1]), "r"((a)[2]), "r"((a)[3]), \
                   "r"((b)[0]), "r"((b)[1]))

// fp32 exp via FMA-pipe exp2 poly (no MUFU bottleneck)
__device__ __forceinline__ float fexp(float x) {
    float t = fmaxf(x * 1.4426950408889634f, -126.0f);
    int i = __float2int_rd(t);
    float f = t - (float)i;
    float p = 1.f + f * (0.69314718f + f * (0.24022651f + f * (0.05550411f +
              f * (0.00961812f + f * 0.00133336f))));
    return __int_as_float((i + 127) << 23) * p;
}

// ---------------- bf16 tensor-core GEMM: C[m][n] = epi(sum_k A[m][k]*B[n][k]) --
// Block MT x NT, WM x WN warps, warp tile (MT/WM) x (NT/WN),
// K-chunk 64 (128B rows, swizzle seg^(row&7)), 3-stage cp.async pipeline.
struct GP {
    const __nv_bfloat16 *A, *B;
    float* Cf; __nv_bfloat16* Cb;
    int K, lda, ldb, ldc, Mrows, zInner, act, perm;
    long sAo, sAi, sBo, sBi, sCo, sCi;
    const float *bias, *add, *res, *alpha, *rowScale;
    float* rsum;
    float scale;
};

template <int MT, int NT, int WM, int WN>
__global__ void __launch_bounds__(WM * WN * 32) tgemm_k(GP g)
{
    constexpr int THREADS = WM * WN * 32;
    constexpr int MSPAN = MT / WM, NSPAN = NT / WN;
    constexpr int MTW = MSPAN / 16, NSUB = NSPAN / 8;
    constexpr int SMA = MT * 128;
    constexpr int SMB = NT * 128;
    constexpr int AIT = MT * 8 / THREADS, BIT = NT * 8 / THREADS;
    extern __shared__ __align__(128) uint8_t dyn[];
    const uint32_t smA_u = smem_u32(dyn);
    const uint32_t smB_u = smA_u + 3 * SMA;

    int tid = threadIdx.x, wid = tid >> 5, lid = tid & 31;
    int wm = wid % WM, wn = wid / WM;
    int z = blockIdx.z, zo = z / g.zInner, zi = z - zo * g.zInner;
    const __nv_bfloat16* Ab = g.A + zo * g.sAo + zi * g.sAi + (long)blockIdx.x * MT * g.lda;
    const __nv_bfloat16* Bb = g.B + zo * g.sBo + zi * g.sBi + (long)blockIdx.y * NT * g.ldb;
    long cOff = zo * g.sCo + zi * g.sCi;
    int m0 = blockIdx.x * MT, n0 = blockIdx.y * NT;

    float c[MTW][NSUB][4];
#pragma unroll
    for (int mt = 0; mt < MTW; mt++)
#pragma unroll
        for (int s = 0; s < NSUB; s++)
#pragma unroll
            for (int q = 0; q < 4; q++) c[mt][s][q] = 0.f;

    const int nch = g.K >> 6;

    auto issue = [&](int kc, int buf) {
        int kb = kc << 6;
#pragma unroll
        for (int it = 0; it < AIT; it++) {
            int s2 = tid + it * THREADS;
            int row = s2 >> 3, seg = s2 & 7;
            uint32_t d = smA_u + buf * SMA + (((row << 3) + (seg ^ (row & 7))) << 4);
            CP_ASYNC16(d, Ab + (long)row * g.lda + kb + (seg << 3));
        }
#pragma unroll
        for (int it = 0; it < BIT; it++) {
            int s2 = tid + it * THREADS;
            int row = s2 >> 3, seg = s2 & 7;
            uint32_t d = smB_u + buf * SMB + (((row << 3) + (seg ^ (row & 7))) << 4);
            CP_ASYNC16(d, Bb + (long)row * g.ldb + kb + (seg << 3));
        }
        CP_COMMIT();
    };

    if (nch > 0) issue(0, 0);
    if (nch > 1) issue(1, 1);

    int mi = lid >> 3, j = lid & 7;
    int bC = 0, bI = 2;
    for (int kc = 0; kc < nch; kc++) {
        if (kc < nch - 1) asm volatile("cp.async.wait_group 1;" ::: "memory");
        else              asm volatile("cp.async.wait_group 0;" ::: "memory");
        __syncthreads();

        if (kc + 2 < nch) { issue(kc + 2, bI); if (++bI == 3) bI = 0; }

        uint32_t Abase = smA_u + bC * SMA;
        uint32_t Bbase = smB_u + bC * SMB;
#pragma unroll
        for (int ks = 0; ks < 4; ks++) {
            uint32_t aF[MTW][4];
#pragma unroll
            for (int mt = 0; mt < MTW; mt++) {
                int arow = wm * MSPAN + mt * 16 + ((mi & 1) << 3) + j;
                int aseg = (ks << 1) + (mi >> 1);
                uint32_t ad = Abase + (((arow << 3) + (aseg ^ (arow & 7))) << 4);
                LDSM4(aF[mt][0], aF[mt][1], aF[mt][2], aF[mt][3], ad);
            }
            uint32_t bF[NSUB][2];
#pragma unroll
            for (int gi = 0; gi < NSPAN / 16; gi++) {
                int nrow = wn * NSPAN + gi * 16 + ((mi >> 1) << 3) + j;
                int bseg = (ks << 1) + (mi & 1);
                uint32_t bd = Bbase + (((nrow << 3) + (bseg ^ (nrow & 7))) << 4);
                uint32_t r0, r1, r2, r3;
                LDSM4(r0, r1, r2, r3, bd);
                bF[2 * gi][0] = r0; bF[2 * gi][1] = r1;
                bF[2 * gi + 1][0] = r2; bF[2 * gi + 1][1] = r3;
            }
#pragma unroll
            for (int mt = 0; mt < MTW; mt++)
#pragma unroll
                for (int s = 0; s < NSUB; s++)
                    MMA16816(c[mt][s], aF[mt], bF[s]);
        }
        if (++bC == 3) bC = 0;
    }

    // ---- epilogue ----
    float alpha = g.alpha ? *g.alpha : 1.0f;
#pragma unroll
    for (int mt = 0; mt < MTW; mt++) {
        float lsum[2] = {0.f, 0.f};
#pragma unroll
        for (int s = 0; s < NSUB; s++) {
            int rA = m0 + wm * MSPAN + mt * 16 + (lid >> 2);
            int nn = n0 + wn * NSPAN + s * 8 + ((lid & 3) << 1);
#pragma unroll
            for (int hh = 0; hh < 2; hh++) {
                int r = rA + hh * 8;
                float sc = g.scale * (g.rowScale ? g.rowScale[(long)z * g.Mrows + r] : 1.f);
                long rowbase = cOff + (long)r * g.ldc;
#pragma unroll
                for (int w = 0; w < 2; w++) {
                    int n = nn + w;
                    float v = c[mt][s][hh * 2 + w] * sc;
                    if (g.bias) v += __ldg(g.bias + n);
                    long idx = rowbase + n;
                    if (g.add) v += g.add[idx];
                    if (g.act == 1) v = fmaxf(v, 0.f);
                    else if (g.act == 2) v = v > 0.f ? v : 0.01f * v;
                    else if (g.act == 3) v = fexp(v);
                    if (g.rsum) lsum[hh] += v;
                    if (g.res) v = g.res[idx] + alpha * v;
                    if (g.Cf) g.Cf[idx] = v;
                    if (g.Cb) {
                        long bi;
                        if (g.perm == 0) bi = idx;
                        else {
                            int bb = r >> 10, l = r & 1023, h = n >> 6, dd = n & 63;
                            long bh = (bb << 4) + h;
                            bi = (g.perm == 1) ? ((bh << 10) + l) * 64 + dd
                                               : ((bh << 6) + dd) * 1024 + l;
                        }
                        g.Cb[bi] = __float2bfloat16(v);
                    }
                }
            }
        }
        if (g.rsum) {
            int rA = m0 + wm * MSPAN + mt * 16 + (lid >> 2);
#pragma unroll
            for (int hh = 0; hh < 2; hh++) {
                float t = lsum[hh];
                t += __shfl_xor_sync(0xffffffffu, t, 1);
                t += __shfl_xor_sync(0xffffffffu, t, 2);
                if ((lid & 3) == 0)
                    atomicAdd(g.rsum + (long)z * g.Mrows + rA + hh * 8, t);
            }
        }
    }
}

// ---------------- small utility kernels ----------------
__global__ void zero_k(float* __restrict__ p, int n) {
    int i = blockIdx.x * 256 + threadIdx.x;
    if (i < n) p[i] = 0.f;
}
__global__ void recip_k(float* __restrict__ p, int n) {
    int i = blockIdx.x * 256 + threadIdx.x;
    if (i < n) p[i] = 1.0f / p[i];
}

// ---------------- conversions ----------------
__global__ void __launch_bounds__(256) conv_k(const float* __restrict__ s,
                                              __nv_bfloat16* __restrict__ d, long n)
{
    long i = ((long)blockIdx.x * 256 + threadIdx.x) << 2;
    if (i < n) {
        float4 v = *(const float4*)(s + i);
        __nv_bfloat162 lo = __floats2bfloat162_rn(v.x, v.y);
        __nv_bfloat162 hi = __floats2bfloat162_rn(v.z, v.w);
        uint2 u; u.x = *(uint32_t*)&lo; u.y = *(uint32_t*)&hi;
        *(uint2*)(d + i) = u;
    }
}
__global__ void convT_k(const float* __restrict__ s, __nv_bfloat16* __restrict__ d,
                        int R, int C)
{
    __shared__ float t[32][33];
    int c0 = blockIdx.x << 5, r0 = blockIdx.y << 5;
    int x = threadIdx.x, y = threadIdx.y;
#pragma unroll
    for (int i = 0; i < 32; i += 8)
        t[y + i][x] = s[(long)(r0 + y + i) * C + c0 + x];
    __syncthreads();
#pragma unroll
    for (int i = 0; i < 32; i += 8)
        d[(long)(c0 + y + i) * R + r0 + x] = __float2bfloat16(t[x][y + i]);
}
// fused: read tile once -> row-major bf16 copy (d1) AND transposed bf16 (d2)
__global__ void convTB_k(const float* __restrict__ s, __nv_bfloat16* __restrict__ d1,
                         __nv_bfloat16* __restrict__ d2, int R, int C)
{
    __shared__ float t[32][33];
    int c0 = blockIdx.x << 5, r0 = blockIdx.y << 5;
    int x = threadIdx.x, y = threadIdx.y;
#pragma unroll
    for (int i = 0; i < 32; i += 8) {
        float v = s[(long)(r0 + y + i) * C + c0 + x];
        t[y + i][x] = v;
        d1[(long)(r0 + y + i) * C + c0 + x] = __float2bfloat16(v);
    }
    __syncthreads();
#pragma unroll
    for (int i = 0; i < 32; i += 8)
        d2[(long)(c0 + y + i) * R + r0 + x] = __float2bfloat16(t[x][y + i]);
}

// ---------------- host helpers ----------------
static void conv(const float* s, __nv_bfloat16* d, long n) {
    conv_k<<<(unsigned)((n / 4 + 255) / 256), 256>>>(s, d, n);
}
static void convT(const float* s, __nv_bfloat16* d, int R, int C) {
    convT_k<<<dim3(C / 32, R / 32), dim3(32, 8)>>>(s, d, R, C);
}

static void tg(const __nv_bfloat16* A, const __nv_bfloat16* B, float* Cf, __nv_bfloat16* Cb,
               int Mtiles, int Ntot, int K, int lda, int ldb, int ldc, int NT,
               int batch = 1,
               long sAo = 0, long sAi = 0, long sBo = 0, long sBi = 0,
               long sCo = 0, long sCi = 0, int zInner = 1,
               const float* bias = nullptr, const float* add = nullptr,
               const float* res = nullptr, const float* alpha = nullptr,
               const float* rowScale = nullptr, float scale = 1.0f,
               int act = 0, int perm = 0, float* rsum = nullptr,
               int MT = 128)
{
    GP g;
    g.A = A; g.B = B; g.Cf = Cf; g.Cb = Cb;
    g.K = K; g.lda = lda; g.ldb = ldb; g.ldc = ldc;
    g.Mrows = Mtiles * MT; g.zInner = zInner; g.act = act; g.perm = perm;
    g.sAo = sAo; g.sAi = sAi; g.sBo = sBo; g.sBi = sBi; g.sCo = sCo; g.sCi = sCi;
    g.bias = bias; g.add = add; g.res = res; g.alpha = alpha; g.rowScale = rowScale;
    g.rsum = rsum; g.scale = scale;
    dim3 grid(Mtiles, Ntot / NT, batch);
    if (MT == 256) {
        static bool done = false;
        if (!done) {
            cudaFuncSetAttribute(tgemm_k<256, 128, 4, 4>,
                                 cudaFuncAttributeMaxDynamicSharedMemorySize, 3 * 49152);
            done = true;
        }
        tgemm_k<256, 128, 4, 4><<<grid, 512, 3 * 49152>>>(g);
    } else if (NT == 128) {
        static bool done = false;
        if (!done) {
            cudaFuncSetAttribute(tgemm_k<128, 128, 4, 2>,
                                 cudaFuncAttributeMaxDynamicSharedMemorySize, 3 * 32768);
            done = true;
        }
        tgemm_k<128, 128, 4, 2><<<grid, 256, 3 * 32768>>>(g);
    } else {
        static bool done = false;
        if (!done) {
            cudaFuncSetAttribute(tgemm_k<128, 64, 4, 2>,
                                 cudaFuncAttributeMaxDynamicSharedMemorySize, 3 * 24576);
            done = true;
        }
        tgemm_k<128, 64, 4, 2><<<grid, 256, 3 * 24576>>>(g);
    }
}

extern "C" void kernel_launch(void* const* d_in, const int* in_sizes, int n_in,
                              void* d_out, int out_size)
{
    const float* tgt   = (const float*)d_in[0];
    const float* src   = (const float*)d_in[1];
    const float* emb   = (const float*)d_in[2];
    const float* va_w  = (const float*)d_in[3];
    const float* va_b  = (const float*)d_in[4];
    const float* a_va  = (const float*)d_in[5];
    const float* sa_wq = (const float*)d_in[6];
    const float* sa_bq = (const float*)d_in[7];
    const float* sa_wk = (const float*)d_in[8];
    const float* sa_bk = (const float*)d_in[9];
    const float* sa_wv = (const float*)d_in[10];
    const float* sa_bv = (const float*)d_in[11];
    const float* sa_wo = (const float*)d_in[12];
    const float* sa_bo = (const float*)d_in[13];
    const float* a_sa  = (const float*)d_in[14];
    const float* ca_wq = (const float*)d_in[15];
    const float* ca_bq = (const float*)d_in[16];
    const float* ca_wk = (const float*)d_in[17];
    const float* ca_bk = (const float*)d_in[18];
    const float* ca_wv = (const float*)d_in[19];
    const float* ca_bv = (const float*)d_in[20];
    const float* ca_wo = (const float*)d_in[21];
    const float* ca_bo = (const float*)d_in[22];
    const float* a_ca  = (const float*)d_in[23];
    const float* ff_w1 = (const float*)d_in[24];
    const float* ff_b1 = (const float*)d_in[25];
    const float* ff_w2 = (const float*)d_in[26];
    const float* ff_b2 = (const float*)d_in[27];
    const float* a_ff  = (const float*)d_in[28];
    float* out = (float*)d_out;

    void* p;
    cudaGetSymbolAddress(&p, g_tmp);  float* tmp  = (float*)p;
    cudaGetSymbolAddress(&p, g_x1);   float* x1   = (float*)p;
    cudaGetSymbolAddress(&p, g_x2);   float* x2   = (float*)p;
    cudaGetSymbolAddress(&p, g_rs);   float* rs   = (float*)p;
    cudaGetSymbolAddress(&p, g_Pb);   __nv_bfloat16* Pb   = (__nv_bfloat16*)p;
    cudaGetSymbolAddress(&p, g_eb);   __nv_bfloat16* eb   = (__nv_bfloat16*)p;
    cudaGetSymbolAddress(&p, g_ebT);  __nv_bfloat16* ebT  = (__nv_bfloat16*)p;
    cudaGetSymbolAddress(&p, g_tgtb); __nv_bfloat16* tgtb = (__nv_bfloat16*)p;
    cudaGetSymbolAddress(&p, g_srcb); __nv_bfloat16* srcb = (__nv_bfloat16*)p;
    cudaGetSymbolAddress(&p, g_avb);  __nv_bfloat16* avb  = (__nv_bfloat16*)p;
    cudaGetSymbolAddress(&p, g_x1b);  __nv_bfloat16* x1b  = (__nv_bfloat16*)p;
    cudaGetSymbolAddress(&p, g_x2b);  __nv_bfloat16* x2b  = (__nv_bfloat16*)p;
    cudaGetSymbolAddress(&p, g_qb);   __nv_bfloat16* qb   = (__nv_bfloat16*)p;
    cudaGetSymbolAddress(&p, g_kb);   __nv_bfloat16* kb   = (__nv_bfloat16*)p;
    cudaGetSymbolAddress(&p, g_vtb);  __nv_bfloat16* vtb  = (__nv_bfloat16*)p;
    cudaGetSymbolAddress(&p, g_yb);   __nv_bfloat16* yb   = (__nv_bfloat16*)p;
    cudaGetSymbolAddress(&p, g_hb);   __nv_bfloat16* hb   = (__nv_bfloat16*)p;
    cudaGetSymbolAddress(&p, g_vawT); __nv_bfloat16* vawT = (__nv_bfloat16*)p;
    cudaGetSymbolAddress(&p, g_wT);   __nv_bfloat16* wT   = (__nv_bfloat16*)p;
    cudaGetSymbolAddress(&p, g_f1T);  __nv_bfloat16* f1T  = (__nv_bfloat16*)p;
    cudaGetSymbolAddress(&p, g_f2T);  __nv_bfloat16* f2T  = (__nv_bfloat16*)p;
    const size_t WSZ = (size_t)DMODEL * DMODEL;

    // fused emb conversion: eb (row-major bf16) + ebT (transposed bf16), one read
    convTB_k<<<dim3(DMODEL / 32, VOCAB / 32), dim3(32, 8)>>>(emb, eb, ebT, VOCAB, DMODEL);
    conv(tgt, tgtb, (long)MD);
    conv(src, srcb, (long)MD);
    zero_k<<<16, 256>>>(rs, 4096);

    const float inv_sd = 1.0f / 32.0f;
    const long sQ = 65536, sS = 1048576;

    // ===== Vocabulary attention (softmax fused; 256-row tiles on the big pair) =
    tg(tgtb, eb, nullptr, Pb, 16, VOCAB, DMODEL, DMODEL, DMODEL, VOCAB, 128,
       1, 0,0,0,0,0,0,1,
       nullptr, nullptr, nullptr, nullptr, nullptr, 1.f, /*exp*/3, 0, rs, /*MT*/256);
    recip_k<<<16, 256>>>(rs, 4096);

    convT(va_w,  vawT,         2 * DMODEL, DMODEL);
    convT(sa_wq, wT + 0 * WSZ, DMODEL, DMODEL);
    convT(sa_wk, wT + 1 * WSZ, DMODEL, DMODEL);
    convT(sa_wv, wT + 2 * WSZ, DMODEL, DMODEL);
    convT(sa_wo, wT + 3 * WSZ, DMODEL, DMODEL);
    convT(ca_wq, wT + 4 * WSZ, DMODEL, DMODEL);
    convT(ca_wk, wT + 5 * WSZ, DMODEL, DMODEL);
    convT(ca_wv, wT + 6 * WSZ, DMODEL, DMODEL);
    convT(ca_wo, wT + 7 * WSZ, DMODEL, DMODEL);
    convT(ff_w1, f1T, DMODEL, DFF);
    convT(ff_w2, f2T, DFF, DMODEL);

    tg(Pb, ebT, nullptr, avb, 16, DMODEL, VOCAB, VOCAB, VOCAB, DMODEL, 128,
       1, 0,0,0,0,0,0,1, nullptr, nullptr, nullptr, nullptr, rs, 1.f, 0, 0,
       nullptr, /*MT*/256);
    tg(avb, vawT + DMODEL, tmp, nullptr, 32, DMODEL, DMODEL, DMODEL, 2 * DMODEL, DMODEL, 128);
    tg(tgtb, vawT, x1, x1b, 32, DMODEL, DMODEL, DMODEL, 2 * DMODEL, DMODEL, 128,
       1, 0,0,0,0,0,0,1, va_b, tmp, tgt, a_va);

    // ===== Self attention =====
    tg(x1b, wT + 0 * WSZ, nullptr, qb, 32, DMODEL, DMODEL, DMODEL, DMODEL, DMODEL, 128,
       1, 0,0,0,0,0,0,1, sa_bq, nullptr, nullptr, nullptr, nullptr, 1.f, 1, 1);
    tg(x1b, wT + 1 * WSZ, nullptr, kb, 32, DMODEL, DMODEL, DMODEL, DMODEL, DMODEL, 128,
       1, 0,0,0,0,0,0,1, sa_bk, nullptr, nullptr, nullptr, nullptr, 1.f, 1, 1);
    tg(x1b, wT + 2 * WSZ, nullptr, vtb, 32, DMODEL, DMODEL, DMODEL, DMODEL, DMODEL, 128,
       1, 0,0,0,0,0,0,1, sa_bv, nullptr, nullptr, nullptr, nullptr, 1.f, 1, 2);
    zero_k<<<256, 256>>>(rs, 65536);
    tg(qb, kb, nullptr, Pb, 8, 1024, 64, 64, 64, 1024, 128,
       64, sQ, 0, sQ, 0, sS, 0, 1,
       nullptr, nullptr, nullptr, nullptr, nullptr, inv_sd, 3, 0, rs);
    recip_k<<<256, 256>>>(rs, 65536);
    tg(Pb, vtb, nullptr, yb, 8, 64, 1024, 1024, 1024, DMODEL, 64,
       64, 16L * sS, sS, 16L * sQ, sQ, (long)1024 * DMODEL, 64, 16,
       nullptr, nullptr, nullptr, nullptr, rs);
    tg(yb, wT + 3 * WSZ, x2, x2b, 32, DMODEL, DMODEL, DMODEL, DMODEL, DMODEL, 128,
       1, 0,0,0,0,0,0,1, sa_bo, nullptr, x1, a_sa, nullptr, 1.f, 1, 0);

    // ===== Cross attention =====
    tg(x2b, wT + 4 * WSZ, nullptr, qb, 32, DMODEL, DMODEL, DMODEL, DMODEL, DMODEL, 128,
       1, 0,0,0,0,0,0,1, ca_bq, nullptr, nullptr, nullptr, nullptr, 1.f, 1, 1);
    tg(srcb, wT + 5 * WSZ, nullptr, kb, 32, DMODEL, DMODEL, DMODEL, DMODEL, DMODEL, 128,
       1, 0,0,0,0,0,0,1, ca_bk, nullptr, nullptr, nullptr, nullptr, 1.f, 1, 1);
    tg(srcb, wT + 6 * WSZ, nullptr, vtb, 32, DMODEL, DMODEL, DMODEL, DMODEL, DMODEL, 128,
       1, 0,0,0,0,0,0,1, ca_bv, nullptr, nullptr, nullptr, nullptr, 1.f, 1, 2);
    zero_k<<<256, 256>>>(rs, 65536);
    tg(qb, kb, nullptr, Pb, 8, 1024, 64, 64, 64, 1024, 128,
       64, sQ, 0, sQ, 0, sS, 0, 1,
       nullptr, nullptr, nullptr, nullptr, nullptr, inv_sd, 3, 0, rs);
    recip_k<<<256, 256>>>(rs, 65536);
    tg(Pb, vtb, nullptr, yb, 8, 64, 1024, 1024, 1024, DMODEL, 64,
       64, 16L * sS, sS, 16L * sQ, sQ, (long)1024 * DMODEL, 64, 16,
       nullptr, nullptr, nullptr, nullptr, rs);
    tg(yb, wT + 7 * WSZ, x1, x1b, 32, DMODEL, DMODEL, DMODEL, DMODEL, DMODEL, 128,
       1, 0,0,0,0,0,0,1, ca_bo, nullptr, x2, a_ca, nullptr, 1.f, 1, 0);

    // ===== Feed forward =====
    tg(x1b, f1T, nullptr, hb, 32, DFF, DMODEL, DMODEL, DMODEL, DFF, 128,
       1, 0,0,0,0,0,0,1, ff_b1, nullptr, nullptr, nullptr, nullptr, 1.f, 2, 0);
    tg(hb, f2T, out, nullptr, 32, DMODEL, DFF, DFF, DFF, DMODEL, 128,
       1, 0,0,0,0,0,0,1, ff_b2, nullptr, x1, a_ff, nullptr, 1.f, 0, 0);
}

// round 16
// speedup vs baseline: 1.0605x; 1.0605x over previous
#include <cuda_runtime.h>
#include <cuda_bf16.h>
#include <cstdint>
#include <math.h>

#define MROWS 4096
#define DMODEL 1024
#define VOCAB 32000
#define DFF 2048
#define MD ((size_t)MROWS * DMODEL)

// ---------------- scratch (allocation-free rule) ----------------
__device__ float g_x1[MD], g_x2[MD];
__device__ float g_rs[65536];
__device__ __nv_bfloat16 g_Pb[(size_t)MROWS * VOCAB];
__device__ __nv_bfloat16 g_eb[(size_t)VOCAB * DMODEL];
__device__ __nv_bfloat16 g_ebT[(size_t)VOCAB * DMODEL];
__device__ __nv_bfloat16 g_cat[(size_t)MROWS * 2 * DMODEL];   // [tgt | A_v] bf16
__device__ __nv_bfloat16 g_srcb[MD], g_x1b[MD], g_x2b[MD];
__device__ __nv_bfloat16 g_qb[MD], g_kb[MD], g_vtb[MD], g_yb[MD];
__device__ __nv_bfloat16 g_hb[(size_t)MROWS * DFF];
__device__ __nv_bfloat16 g_vawT[(size_t)2 * DMODEL * DMODEL];
__device__ __nv_bfloat16 g_wT[8][(size_t)DMODEL * DMODEL];
__device__ __nv_bfloat16 g_f1T[(size_t)DFF * DMODEL];
__device__ __nv_bfloat16 g_f2T[(size_t)DFF * DMODEL];

// ---------------- PTX helpers ----------------
__device__ __forceinline__ uint32_t smem_u32(const void* p) {
    uint32_t a;
    asm("{ .reg .u64 t; cvta.to.shared.u64 t, %1; cvt.u32.u64 %0, t; }" : "=r"(a) : "l"(p));
    return a;
}
#define CP_ASYNC16(dst, src) \
    asm volatile("cp.async.cg.shared.global [%0], [%1], 16;" \
                 :: "r"(dst), "l"(__cvta_generic_to_global(src)) : "memory")
#define CP_COMMIT() asm volatile("cp.async.commit_group;" ::: "memory")
#define LDSM4(r0, r1, r2, r3, a) \
    asm volatile("ldmatrix.sync.aligned.m8n8.x4.shared.b16 {%0,%1,%2,%3}, [%4];" \
                 : "=r"(r0), "=r"(r1), "=r"(r2), "=r"(r3) : "r"(a))
#define MMA16816(c, a, b) \
    asm volatile("mma.sync.aligned.m16n8k16.row.col.f32.bf16.bf16.f32 " \
                 "{%0,%1,%2,%3}, {%4,%5,%6,%7}, {%8,%9}, {%0,%1,%2,%3};" \
                 : "+f"((c)[0]), "+f"((c)[1]), "+f"((c)[2]), "+f"((c)[3]) \
                 : "r"((a)[0]), "r"((a)[1]), "r"((a)[2]), "r"((a)[3]), \
                   "r"((b)[0]), "r"((b)[1]))

// fp32 exp via FMA-pipe exp2 poly (no MUFU bottleneck)
__device__ __forceinline__ float fexp(float x) {
    float t = fmaxf(x * 1.4426950408889634f, -126.0f);
    int i = __float2int_rd(t);
    float f = t - (float)i;
    float p = 1.f + f * (0.69314718f + f * (0.24022651f + f * (0.05550411f +
              f * (0.00961812f + f * 0.00133336f))));
    return __int_as_float((i + 127) << 23) * p;
}

// ---------------- bf16 tensor-core GEMM: C[m][n] = epi(sum_k A[m][k]*B[n][k]) --
// Block 128 x NT, 8 warps (4M x 2N), warp tile 32 x NT/2,
// K-chunk 64 (128B rows, swizzle seg^(row&7)), 3-stage cp.async pipeline.
struct GP {
    const __nv_bfloat16 *A, *B;
    float* Cf; __nv_bfloat16* Cb;
    int K, lda, ldb, ldc, Mrows, zInner, act, perm;
    long sAo, sAi, sBo, sBi, sCo, sCi;
    const float *bias, *add, *res, *alpha, *rowScale;
    float* rsum;
    float scale;
};

template <int NT>
__global__ void __launch_bounds__(256) tgemm_k(GP g)
{
    constexpr int NSUB = NT / 16;
    constexpr int SMA = 16384;          // 128 rows x 128B
    constexpr int SMB = NT * 128;
    extern __shared__ __align__(128) uint8_t dyn[];
    const uint32_t smA_u = smem_u32(dyn);
    const uint32_t smB_u = smA_u + 3 * SMA;

    int tid = threadIdx.x, wid = tid >> 5, lid = tid & 31;
    int wm = wid & 3, wn = wid >> 2;
    int z = blockIdx.z, zo = z / g.zInner, zi = z - zo * g.zInner;
    const __nv_bfloat16* Ab = g.A + zo * g.sAo + zi * g.sAi + (long)blockIdx.x * 128 * g.lda;
    const __nv_bfloat16* Bb = g.B + zo * g.sBo + zi * g.sBi + (long)blockIdx.y * NT * g.ldb;
    long cOff = zo * g.sCo + zi * g.sCi;
    int m0 = blockIdx.x * 128, n0 = blockIdx.y * NT;

    float c[2][NSUB][4];
#pragma unroll
    for (int mt = 0; mt < 2; mt++)
#pragma unroll
        for (int s = 0; s < NSUB; s++)
#pragma unroll
            for (int q = 0; q < 4; q++) c[mt][s][q] = 0.f;

    const int nch = g.K >> 6;

    auto issue = [&](int kc, int buf) {
        int kb = kc << 6;
#pragma unroll
        for (int it = 0; it < 4; it++) {
            int s2 = tid + (it << 8);
            int row = s2 >> 3, seg = s2 & 7;
            uint32_t d = smA_u + buf * SMA + (((row << 3) + (seg ^ (row & 7))) << 4);
            CP_ASYNC16(d, Ab + (long)row * g.lda + kb + (seg << 3));
        }
#pragma unroll
        for (int it = 0; it < NT / 32; it++) {
            int s2 = tid + (it << 8);
            int row = s2 >> 3, seg = s2 & 7;
            uint32_t d = smB_u + buf * SMB + (((row << 3) + (seg ^ (row & 7))) << 4);
            CP_ASYNC16(d, Bb + (long)row * g.ldb + kb + (seg << 3));
        }
        CP_COMMIT();
    };

    if (nch > 0) issue(0, 0);
    if (nch > 1) issue(1, 1);

    int mi = lid >> 3, j = lid & 7;
    int bC = 0, bI = 2;
    for (int kc = 0; kc < nch; kc++) {
        if (kc < nch - 1) asm volatile("cp.async.wait_group 1;" ::: "memory");
        else              asm volatile("cp.async.wait_group 0;" ::: "memory");
        __syncthreads();

        if (kc + 2 < nch) { issue(kc + 2, bI); if (++bI == 3) bI = 0; }

        uint32_t Abase = smA_u + bC * SMA;
        uint32_t Bbase = smB_u + bC * SMB;
#pragma unroll
        for (int ks = 0; ks < 4; ks++) {
            uint32_t aF[2][4];
#pragma unroll
            for (int mt = 0; mt < 2; mt++) {
                int arow = wm * 32 + mt * 16 + ((mi & 1) << 3) + j;
                int aseg = (ks << 1) + (mi >> 1);
                uint32_t ad = Abase + (((arow << 3) + (aseg ^ (arow & 7))) << 4);
                LDSM4(aF[mt][0], aF[mt][1], aF[mt][2], aF[mt][3], ad);
            }
            uint32_t bF[NSUB][2];
#pragma unroll
            for (int gi = 0; gi < NT / 32; gi++) {
                int nrow = wn * (NT / 2) + gi * 16 + ((mi >> 1) << 3) + j;
                int bseg = (ks << 1) + (mi & 1);
                uint32_t bd = Bbase + (((nrow << 3) + (bseg ^ (nrow & 7))) << 4);
                uint32_t r0, r1, r2, r3;
                LDSM4(r0, r1, r2, r3, bd);
                bF[2 * gi][0] = r0; bF[2 * gi][1] = r1;
                bF[2 * gi + 1][0] = r2; bF[2 * gi + 1][1] = r3;
            }
#pragma unroll
            for (int mt = 0; mt < 2; mt++)
#pragma unroll
                for (int s = 0; s < NSUB; s++)
                    MMA16816(c[mt][s], aF[mt], bF[s]);
        }
        if (++bC == 3) bC = 0;
    }

    // ---- epilogue ----
    float alpha = g.alpha ? *g.alpha : 1.0f;
#pragma unroll
    for (int mt = 0; mt < 2; mt++) {
        float lsum[2] = {0.f, 0.f};
#pragma unroll
        for (int s = 0; s < NSUB; s++) {
            int rA = m0 + wm * 32 + mt * 16 + (lid >> 2);
            int nn = n0 + wn * (NT / 2) + s * 8 + ((lid & 3) << 1);
#pragma unroll
            for (int hh = 0; hh < 2; hh++) {
                int r = rA + hh * 8;
                float sc = g.scale * (g.rowScale ? g.rowScale[(long)z * g.Mrows + r] : 1.f);
                long rowbase = cOff + (long)r * g.ldc;
#pragma unroll
                for (int w = 0; w < 2; w++) {
                    int n = nn + w;
                    float v = c[mt][s][hh * 2 + w] * sc;
                    if (g.bias) v += __ldg(g.bias + n);
                    long idx = rowbase + n;
                    if (g.add) v += g.add[idx];
                    if (g.act == 1) v = fmaxf(v, 0.f);
                    else if (g.act == 2) v = v > 0.f ? v : 0.01f * v;
                    else if (g.act == 3) v = fexp(v);
                    if (g.rsum) lsum[hh] += v;
                    if (g.res) v = g.res[idx] + alpha * v;
                    if (g.Cf) g.Cf[idx] = v;
                    if (g.Cb) {
                        long bi;
                        if (g.perm == 0) bi = idx;
                        else {
                            int bb = r >> 10, l = r & 1023, h = n >> 6, dd = n & 63;
                            long bh = (bb << 4) + h;
                            bi = (g.perm == 1) ? ((bh << 10) + l) * 64 + dd
                                               : ((bh << 6) + dd) * 1024 + l;
                        }
                        g.Cb[bi] = __float2bfloat16(v);
                    }
                }
            }
        }
        if (g.rsum) {
            int rA = m0 + wm * 32 + mt * 16 + (lid >> 2);
#pragma unroll
            for (int hh = 0; hh < 2; hh++) {
                float t = lsum[hh];
                t += __shfl_xor_sync(0xffffffffu, t, 1);
                t += __shfl_xor_sync(0xffffffffu, t, 2);
                if ((lid & 3) == 0)
                    atomicAdd(g.rsum + (long)z * g.Mrows + rA + hh * 8, t);
            }
        }
    }
}

// ---------------- small utility kernels ----------------
__global__ void zero_k(float* __restrict__ p, int n) {
    int i = blockIdx.x * 256 + threadIdx.x;
    if (i < n) p[i] = 0.f;
}
__global__ void recip_k(float* __restrict__ p, int n) {
    int i = blockIdx.x * 256 + threadIdx.x;
    if (i < n) p[i] = 1.0f / p[i];
}

// ---------------- conversions ----------------
__global__ void __launch_bounds__(256) conv_k(const float* __restrict__ s,
                                              __nv_bfloat16* __restrict__ d, long n)
{
    long i = ((long)blockIdx.x * 256 + threadIdx.x) << 2;
    if (i < n) {
        float4 v = *(const float4*)(s + i);
        __nv_bfloat162 lo = __floats2bfloat162_rn(v.x, v.y);
        __nv_bfloat162 hi = __floats2bfloat162_rn(v.z, v.w);
        uint2 u; u.x = *(uint32_t*)&lo; u.y = *(uint32_t*)&hi;
        *(uint2*)(d + i) = u;
    }
}
// strided conv: src [rows,1024] fp32 row-major -> dst bf16 rows with ld=2048
__global__ void __launch_bounds__(256) conv_st_k(const float* __restrict__ s,
                                                 __nv_bfloat16* __restrict__ d, long n)
{
    long i = ((long)blockIdx.x * 256 + threadIdx.x) << 2;
    if (i < n) {
        float4 v = *(const float4*)(s + i);
        __nv_bfloat162 lo = __floats2bfloat162_rn(v.x, v.y);
        __nv_bfloat162 hi = __floats2bfloat162_rn(v.z, v.w);
        uint2 u; u.x = *(uint32_t*)&lo; u.y = *(uint32_t*)&hi;
        long row = i >> 10, col = i & 1023;
        *(uint2*)(d + row * 2048 + col) = u;
    }
}
__global__ void convT_k(const float* __restrict__ s, __nv_bfloat16* __restrict__ d,
                        int R, int C)
{
    __shared__ float t[32][33];
    int c0 = blockIdx.x << 5, r0 = blockIdx.y << 5;
    int x = threadIdx.x, y = threadIdx.y;
#pragma unroll
    for (int i = 0; i < 32; i += 8)
        t[y + i][x] = s[(long)(r0 + y + i) * C + c0 + x];
    __syncthreads();
#pragma unroll
    for (int i = 0; i < 32; i += 8)
        d[(long)(c0 + y + i) * R + r0 + x] = __float2bfloat16(t[x][y + i]);
}
// fused: read tile once -> row-major bf16 copy (d1) AND transposed bf16 (d2)
__global__ void convTB_k(const float* __restrict__ s, __nv_bfloat16* __restrict__ d1,
                         __nv_bfloat16* __restrict__ d2, int R, int C)
{
    __shared__ float t[32][33];
    int c0 = blockIdx.x << 5, r0 = blockIdx.y << 5;
    int x = threadIdx.x, y = threadIdx.y;
#pragma unroll
    for (int i = 0; i < 32; i += 8) {
        float v = s[(long)(r0 + y + i) * C + c0 + x];
        t[y + i][x] = v;
        d1[(long)(r0 + y + i) * C + c0 + x] = __float2bfloat16(v);
    }
    __syncthreads();
#pragma unroll
    for (int i = 0; i < 32; i += 8)
        d2[(long)(c0 + y + i) * R + r0 + x] = __float2bfloat16(t[x][y + i]);
}

// ---------------- host helpers ----------------
static void conv(const float* s, __nv_bfloat16* d, long n) {
    conv_k<<<(unsigned)((n / 4 + 255) / 256), 256>>>(s, d, n);
}
static void convT(const float* s, __nv_bfloat16* d, int R, int C) {
    convT_k<<<dim3(C / 32, R / 32), dim3(32, 8)>>>(s, d, R, C);
}

static void tg(const __nv_bfloat16* A, const __nv_bfloat16* B, float* Cf, __nv_bfloat16* Cb,
               int Mtiles, int Ntot, int K, int lda, int ldb, int ldc, int NT,
               int batch = 1,
               long sAo = 0, long sAi = 0, long sBo = 0, long sBi = 0,
               long sCo = 0, long sCi = 0, int zInner = 1,
               const float* bias = nullptr, const float* add = nullptr,
               const float* res = nullptr, const float* alpha = nullptr,
               const float* rowScale = nullptr, float scale = 1.0f,
               int act = 0, int perm = 0, float* rsum = nullptr)
{
    GP g;
    g.A = A; g.B = B; g.Cf = Cf; g.Cb = Cb;
    g.K = K; g.lda = lda; g.ldb = ldb; g.ldc = ldc;
    g.Mrows = Mtiles * 128; g.zInner = zInner; g.act = act; g.perm = perm;
    g.sAo = sAo; g.sAi = sAi; g.sBo = sBo; g.sBi = sBi; g.sCo = sCo; g.sCi = sCi;
    g.bias = bias; g.add = add; g.res = res; g.alpha = alpha; g.rowScale = rowScale;
    g.rsum = rsum; g.scale = scale;
    dim3 grid(Mtiles, Ntot / NT, batch);
    if (NT == 128) {
        static bool done = false;
        if (!done) {
            cudaFuncSetAttribute(tgemm_k<128>,
                                 cudaFuncAttributeMaxDynamicSharedMemorySize, 3 * 32768);
            done = true;
        }
        tgemm_k<128><<<grid, 256, 3 * 32768>>>(g);
    } else {
        static bool done = false;
        if (!done) {
            cudaFuncSetAttribute(tgemm_k<64>,
                                 cudaFuncAttributeMaxDynamicSharedMemorySize, 3 * 24576);
            done = true;
        }
        tgemm_k<64><<<grid, 256, 3 * 24576>>>(g);
    }
}

extern "C" void kernel_launch(void* const* d_in, const int* in_sizes, int n_in,
                              void* d_out, int out_size)
{
    const float* tgt   = (const float*)d_in[0];
    const float* src   = (const float*)d_in[1];
    const float* emb   = (const float*)d_in[2];
    const float* va_w  = (const float*)d_in[3];
    const float* va_b  = (const float*)d_in[4];
    const float* a_va  = (const float*)d_in[5];
    const float* sa_wq = (const float*)d_in[6];
    const float* sa_bq = (const float*)d_in[7];
    const float* sa_wk = (const float*)d_in[8];
    const float* sa_bk = (const float*)d_in[9];
    const float* sa_wv = (const float*)d_in[10];
    const float* sa_bv = (const float*)d_in[11];
    const float* sa_wo = (const float*)d_in[12];
    const float* sa_bo = (const float*)d_in[13];
    const float* a_sa  = (const float*)d_in[14];
    const float* ca_wq = (const float*)d_in[15];
    const float* ca_bq = (const float*)d_in[16];
    const float* ca_wk = (const float*)d_in[17];
    const float* ca_bk = (const float*)d_in[18];
    const float* ca_wv = (const float*)d_in[19];
    const float* ca_bv = (const float*)d_in[20];
    const float* ca_wo = (const float*)d_in[21];
    const float* ca_bo = (const float*)d_in[22];
    const float* a_ca  = (const float*)d_in[23];
    const float* ff_w1 = (const float*)d_in[24];
    const float* ff_b1 = (const float*)d_in[25];
    const float* ff_w2 = (const float*)d_in[26];
    const float* ff_b2 = (const float*)d_in[27];
    const float* a_ff  = (const float*)d_in[28];
    float* out = (float*)d_out;

    void* p;
    cudaGetSymbolAddress(&p, g_x1);   float* x1   = (float*)p;
    cudaGetSymbolAddress(&p, g_x2);   float* x2   = (float*)p;
    cudaGetSymbolAddress(&p, g_rs);   float* rs   = (float*)p;
    cudaGetSymbolAddress(&p, g_Pb);   __nv_bfloat16* Pb   = (__nv_bfloat16*)p;
    cudaGetSymbolAddress(&p, g_eb);   __nv_bfloat16* eb   = (__nv_bfloat16*)p;
    cudaGetSymbolAddress(&p, g_ebT);  __nv_bfloat16* ebT  = (__nv_bfloat16*)p;
    cudaGetSymbolAddress(&p, g_cat);  __nv_bfloat16* catb = (__nv_bfloat16*)p;
    cudaGetSymbolAddress(&p, g_srcb); __nv_bfloat16* srcb = (__nv_bfloat16*)p;
    cudaGetSymbolAddress(&p, g_x1b);  __nv_bfloat16* x1b  = (__nv_bfloat16*)p;
    cudaGetSymbolAddress(&p, g_x2b);  __nv_bfloat16* x2b  = (__nv_bfloat16*)p;
    cudaGetSymbolAddress(&p, g_qb);   __nv_bfloat16* qb   = (__nv_bfloat16*)p;
    cudaGetSymbolAddress(&p, g_kb);   __nv_bfloat16* kb   = (__nv_bfloat16*)p;
    cudaGetSymbolAddress(&p, g_vtb);  __nv_bfloat16* vtb  = (__nv_bfloat16*)p;
    cudaGetSymbolAddress(&p, g_yb);   __nv_bfloat16* yb   = (__nv_bfloat16*)p;
    cudaGetSymbolAddress(&p, g_hb);   __nv_bfloat16* hb   = (__nv_bfloat16*)p;
    cudaGetSymbolAddress(&p, g_vawT); __nv_bfloat16* vawT = (__nv_bfloat16*)p;
    cudaGetSymbolAddress(&p, g_wT);   __nv_bfloat16* wT   = (__nv_bfloat16*)p;
    cudaGetSymbolAddress(&p, g_f1T);  __nv_bfloat16* f1T  = (__nv_bfloat16*)p;
    cudaGetSymbolAddress(&p, g_f2T);  __nv_bfloat16* f2T  = (__nv_bfloat16*)p;
    const size_t WSZ = (size_t)DMODEL * DMODEL;

    // fused emb conversion: eb (row-major bf16) + ebT (transposed bf16), one read
    convTB_k<<<dim3(DMODEL / 32, VOCAB / 32), dim3(32, 8)>>>(emb, eb, ebT, VOCAB, DMODEL);
    // tgt -> cat cols [0,1024) (stride 2048)
    conv_st_k<<<(unsigned)(MD / 4 / 256), 256>>>(tgt, catb, (long)MD);
    conv(src, srcb, (long)MD);
    zero_k<<<16, 256>>>(rs, 4096);

    const float inv_sd = 1.0f / 32.0f;
    const long sQ = 65536, sS = 1048576;

    // ===== Vocabulary attention (softmax fused: exp in epilogue + row sums) ====
    tg(catb, eb, nullptr, Pb, 32, VOCAB, DMODEL, /*lda*/2 * DMODEL, DMODEL, VOCAB, 128,
       1, 0,0,0,0,0,0,1,
       nullptr, nullptr, nullptr, nullptr, nullptr, 1.f, /*exp*/3, 0, rs);
    recip_k<<<16, 256>>>(rs, 4096);

    convT(va_w,  vawT,         2 * DMODEL, DMODEL);
    convT(sa_wq, wT + 0 * WSZ, DMODEL, DMODEL);
    convT(sa_wk, wT + 1 * WSZ, DMODEL, DMODEL);
    convT(sa_wv, wT + 2 * WSZ, DMODEL, DMODEL);
    convT(sa_wo, wT + 3 * WSZ, DMODEL, DMODEL);
    convT(ca_wq, wT + 4 * WSZ, DMODEL, DMODEL);
    convT(ca_wk, wT + 5 * WSZ, DMODEL, DMODEL);
    convT(ca_wv, wT + 6 * WSZ, DMODEL, DMODEL);
    convT(ca_wo, wT + 7 * WSZ, DMODEL, DMODEL);
    convT(ff_w1, f1T, DMODEL, DFF);
    convT(ff_w2, f2T, DFF, DMODEL);

    // A_v = softmax(P)@E -> cat cols [1024,2048)  (bf16, ldc=2048, rowScale=1/sum)
    tg(Pb, ebT, nullptr, catb + DMODEL, 32, DMODEL, VOCAB, VOCAB, VOCAB, 2 * DMODEL, 128,
       1, 0,0,0,0,0,0,1, nullptr, nullptr, nullptr, nullptr, rs);
    // x1 = tgt + alpha_va * (cat @ vawT + va_b)   (single K=2048 GEMM)
    tg(catb, vawT, x1, x1b, 32, DMODEL, 2 * DMODEL, 2 * DMODEL, 2 * DMODEL, DMODEL, 128,
       1, 0,0,0,0,0,0,1, va_b, nullptr, tgt, a_va);

    // ===== Self attention =====
    tg(x1b, wT + 0 * WSZ, nullptr, qb, 32, DMODEL, DMODEL, DMODEL, DMODEL, DMODEL, 128,
       1, 0,0,0,0,0,0,1, sa_bq, nullptr, nullptr, nullptr, nullptr, 1.f, 1, 1);
    tg(x1b, wT + 1 * WSZ, nullptr, kb, 32, DMODEL, DMODEL, DMODEL, DMODEL, DMODEL, 128,
       1, 0,0,0,0,0,0,1, sa_bk, nullptr, nullptr, nullptr, nullptr, 1.f, 1, 1);
    tg(x1b, wT + 2 * WSZ, nullptr, vtb, 32, DMODEL, DMODEL, DMODEL, DMODEL, DMODEL, 128,
       1, 0,0,0,0,0,0,1, sa_bv, nullptr, nullptr, nullptr, nullptr, 1.f, 1, 2);
    zero_k<<<256, 256>>>(rs, 65536);
    tg(qb, kb, nullptr, Pb, 8, 1024, 64, 64, 64, 1024, 128,
       64, sQ, 0, sQ, 0, sS, 0, 1,
       nullptr, nullptr, nullptr, nullptr, nullptr, inv_sd, 3, 0, rs);
    recip_k<<<256, 256>>>(rs, 65536);
    tg(Pb, vtb, nullptr, yb, 8, 64, 1024, 1024, 1024, DMODEL, 64,
       64, 16L * sS, sS, 16L * sQ, sQ, (long)1024 * DMODEL, 64, 16,
       nullptr, nullptr, nullptr, nullptr, rs);
    tg(yb, wT + 3 * WSZ, x2, x2b, 32, DMODEL, DMODEL, DMODEL, DMODEL, DMODEL, 128,
       1, 0,0,0,0,0,0,1, sa_bo, nullptr, x1, a_sa, nullptr, 1.f, 1, 0);

    // ===== Cross attention =====
    tg(x2b, wT + 4 * WSZ, nullptr, qb, 32, DMODEL, DMODEL, DMODEL, DMODEL, DMODEL, 128,
       1, 0,0,0,0,0,0,1, ca_bq, nullptr, nullptr, nullptr, nullptr, 1.f, 1, 1);
    tg(srcb, wT + 5 * WSZ, nullptr, kb, 32, DMODEL, DMODEL, DMODEL, DMODEL, DMODEL, 128,
       1, 0,0,0,0,0,0,1, ca_bk, nullptr, nullptr, nullptr, nullptr, 1.f, 1, 1);
    tg(srcb, wT + 6 * WSZ, nullptr, vtb, 32, DMODEL, DMODEL, DMODEL, DMODEL, DMODEL, 128,
       1, 0,0,0,0,0,0,1, ca_bv, nullptr, nullptr, nullptr, nullptr, 1.f, 1, 2);
    zero_k<<<256, 256>>>(rs, 65536);
    tg(qb, kb, nullptr, Pb, 8, 1024, 64, 64, 64, 1024, 128,
       64, sQ, 0, sQ, 0, sS, 0, 1,
       nullptr, nullptr, nullptr, nullptr, nullptr, inv_sd, 3, 0, rs);
    recip_k<<<256, 256>>>(rs, 65536);
    tg(Pb, vtb, nullptr, yb, 8, 64, 1024, 1024, 1024, DMODEL, 64,
       64, 16L * sS, sS, 16L * sQ, sQ, (long)1024 * DMODEL, 64, 16,
       nullptr, nullptr, nullptr, nullptr, rs);
    tg(yb, wT + 7 * WSZ, x1, x1b, 32, DMODEL, DMODEL, DMODEL, DMODEL, DMODEL, 128,
       1, 0,0,0,0,0,0,1, ca_bo, nullptr, x2, a_ca, nullptr, 1.f, 1, 0);

    // ===== Feed forward =====
    tg(x1b, f1T, nullptr, hb, 32, DFF, DMODEL, DMODEL, DMODEL, DFF, 128,
       1, 0,0,0,0,0,0,1, ff_b1, nullptr, nullptr, nullptr, nullptr, 1.f, 2, 0);
    tg(hb, f2T, out, nullptr, 32, DMODEL, DFF, DFF, DFF, DMODEL, 128,
       1, 0,0,0,0,0,0,1, ff_b2, nullptr, x1, a_ff, nullptr, 1.f, 0, 0);
}

// round 17
// speedup vs baseline: 1.0840x; 1.0222x over previous
#include <cuda_runtime.h>
#include <cuda_bf16.h>
#include <cstdint>
#include <math.h>

#define MROWS 4096
#define DMODEL 1024
#define VOCAB 32000
#define DFF 2048
#define MD ((size_t)MROWS * DMODEL)

// ---------------- scratch (allocation-free rule) ----------------
__device__ float g_x1[MD], g_x2[MD];
__device__ float g_rs[65536];
__device__ __nv_bfloat16 g_Pb[(size_t)MROWS * VOCAB];
__device__ __nv_bfloat16 g_eb[(size_t)VOCAB * DMODEL];
__device__ __nv_bfloat16 g_ebT[(size_t)VOCAB * DMODEL];
__device__ __nv_bfloat16 g_cat[(size_t)MROWS * 2 * DMODEL];   // [tgt | A_v] bf16
__device__ __nv_bfloat16 g_srcb[MD], g_x1b[MD], g_x2b[MD];
__device__ __nv_bfloat16 g_qb[MD], g_kb[MD], g_vtb[MD], g_yb[MD];
__device__ __nv_bfloat16 g_hb[(size_t)MROWS * DFF];
__device__ __nv_bfloat16 g_vawT[(size_t)2 * DMODEL * DMODEL];
__device__ __nv_bfloat16 g_wT[8][(size_t)DMODEL * DMODEL];
__device__ __nv_bfloat16 g_f1T[(size_t)DFF * DMODEL];
__device__ __nv_bfloat16 g_f2T[(size_t)DFF * DMODEL];

// ---------------- PTX helpers ----------------
__device__ __forceinline__ uint32_t smem_u32(const void* p) {
    uint32_t a;
    asm("{ .reg .u64 t; cvta.to.shared.u64 t, %1; cvt.u32.u64 %0, t; }" : "=r"(a) : "l"(p));
    return a;
}
#define CP_ASYNC16(dst, src) \
    asm volatile("cp.async.cg.shared.global [%0], [%1], 16;" \
                 :: "r"(dst), "l"(__cvta_generic_to_global(src)) : "memory")
#define CP_COMMIT() asm volatile("cp.async.commit_group;" ::: "memory")
#define LDSM4(r0, r1, r2, r3, a) \
    asm volatile("ldmatrix.sync.aligned.m8n8.x4.shared.b16 {%0,%1,%2,%3}, [%4];" \
                 : "=r"(r0), "=r"(r1), "=r"(r2), "=r"(r3) : "r"(a))
#define MMA16816(c, a, b) \
    asm volatile("mma.sync.aligned.m16n8k16.row.col.f32.bf16.bf16.f32 " \
                 "{%0,%1,%2,%3}, {%4,%5,%6,%7}, {%8,%9}, {%0,%1,%2,%3};" \
                 : "+f"((c)[0]), "+f"((c)[1]), "+f"((c)[2]), "+f"((c)[3]) \
                 : "r"((a)[0]), "r"((a)[1]), "r"((a)[2]), "r"((a)[3]), \
                   "r"((b)[0]), "r"((b)[1]))

// fp32 exp via FMA-pipe exp2 poly (no MUFU bottleneck)
__device__ __forceinline__ float fexp(float x) {
    float t = fmaxf(x * 1.4426950408889634f, -126.0f);
    int i = __float2int_rd(t);
    float f = t - (float)i;
    float p = 1.f + f * (0.69314718f + f * (0.24022651f + f * (0.05550411f +
              f * (0.00961812f + f * 0.00133336f))));
    return __int_as_float((i + 127) << 23) * p;
}

// ---------------- bf16 tensor-core GEMM: C[m][n] = epi(sum_k A[m][k]*B[n][k]) --
// Block 128 x NT, 8 warps (4M x 2N), warp tile 32 x NT/2,
// K-chunk 64 (128B rows, swizzle seg^(row&7)), 3-stage cp.async pipeline.
struct GP {
    const __nv_bfloat16 *A, *B;
    float* Cf; __nv_bfloat16* Cb;
    int K, lda, ldb, ldc, Mrows, zInner, act, perm;
    long sAo, sAi, sBo, sBi, sCo, sCi;
    const float *bias, *add, *res, *alpha, *rowScale;
    float* rsum;
    float scale;
};

template <int NT>
__global__ void __launch_bounds__(256) tgemm_k(GP g)
{
    constexpr int NSUB = NT / 16;
    constexpr int SMA = 16384;          // 128 rows x 128B
    constexpr int SMB = NT * 128;
    extern __shared__ __align__(128) uint8_t dyn[];
    const uint32_t smA_u = smem_u32(dyn);
    const uint32_t smB_u = smA_u + 3 * SMA;

    int tid = threadIdx.x, wid = tid >> 5, lid = tid & 31;
    int wm = wid & 3, wn = wid >> 2;
    int z = blockIdx.z, zo = z / g.zInner, zi = z - zo * g.zInner;
    const __nv_bfloat16* Ab = g.A + zo * g.sAo + zi * g.sAi + (long)blockIdx.x * 128 * g.lda;
    const __nv_bfloat16* Bb = g.B + zo * g.sBo + zi * g.sBi + (long)blockIdx.y * NT * g.ldb;
    long cOff = zo * g.sCo + zi * g.sCi;
    int m0 = blockIdx.x * 128, n0 = blockIdx.y * NT;

    float c[2][NSUB][4];
#pragma unroll
    for (int mt = 0; mt < 2; mt++)
#pragma unroll
        for (int s = 0; s < NSUB; s++)
#pragma unroll
            for (int q = 0; q < 4; q++) c[mt][s][q] = 0.f;

    const int nch = g.K >> 6;

    auto issue = [&](int kc, int buf) {
        int kb = kc << 6;
#pragma unroll
        for (int it = 0; it < 4; it++) {
            int s2 = tid + (it << 8);
            int row = s2 >> 3, seg = s2 & 7;
            uint32_t d = smA_u + buf * SMA + (((row << 3) + (seg ^ (row & 7))) << 4);
            CP_ASYNC16(d, Ab + (long)row * g.lda + kb + (seg << 3));
        }
#pragma unroll
        for (int it = 0; it < NT / 32; it++) {
            int s2 = tid + (it << 8);
            int row = s2 >> 3, seg = s2 & 7;
            uint32_t d = smB_u + buf * SMB + (((row << 3) + (seg ^ (row & 7))) << 4);
            CP_ASYNC16(d, Bb + (long)row * g.ldb + kb + (seg << 3));
        }
        CP_COMMIT();
    };

    if (nch > 0) issue(0, 0);
    if (nch > 1) issue(1, 1);

    int mi = lid >> 3, j = lid & 7;
    int bC = 0, bI = 2;
    for (int kc = 0; kc < nch; kc++) {
        if (kc < nch - 1) asm volatile("cp.async.wait_group 1;" ::: "memory");
        else              asm volatile("cp.async.wait_group 0;" ::: "memory");
        __syncthreads();

        if (kc + 2 < nch) { issue(kc + 2, bI); if (++bI == 3) bI = 0; }

        uint32_t Abase = smA_u + bC * SMA;
        uint32_t Bbase = smB_u + bC * SMB;
#pragma unroll
        for (int ks = 0; ks < 4; ks++) {
            uint32_t aF[2][4];
#pragma unroll
            for (int mt = 0; mt < 2; mt++) {
                int arow = wm * 32 + mt * 16 + ((mi & 1) << 3) + j;
                int aseg = (ks << 1) + (mi >> 1);
                uint32_t ad = Abase + (((arow << 3) + (aseg ^ (arow & 7))) << 4);
                LDSM4(aF[mt][0], aF[mt][1], aF[mt][2], aF[mt][3], ad);
            }
            uint32_t bF[NSUB][2];
#pragma unroll
            for (int gi = 0; gi < NT / 32; gi++) {
                int nrow = wn * (NT / 2) + gi * 16 + ((mi >> 1) << 3) + j;
                int bseg = (ks << 1) + (mi & 1);
                uint32_t bd = Bbase + (((nrow << 3) + (bseg ^ (nrow & 7))) << 4);
                uint32_t r0, r1, r2, r3;
                LDSM4(r0, r1, r2, r3, bd);
                bF[2 * gi][0] = r0; bF[2 * gi][1] = r1;
                bF[2 * gi + 1][0] = r2; bF[2 * gi + 1][1] = r3;
            }
#pragma unroll
            for (int mt = 0; mt < 2; mt++)
#pragma unroll
                for (int s = 0; s < NSUB; s++)
                    MMA16816(c[mt][s], aF[mt], bF[s]);
        }
        if (++bC == 3) bC = 0;
    }

    // ---- epilogue ----
    float alpha = g.alpha ? *g.alpha : 1.0f;
#pragma unroll
    for (int mt = 0; mt < 2; mt++) {
        float lsum[2] = {0.f, 0.f};
#pragma unroll
        for (int s = 0; s < NSUB; s++) {
            int rA = m0 + wm * 32 + mt * 16 + (lid >> 2);
            int nn = n0 + wn * (NT / 2) + s * 8 + ((lid & 3) << 1);
#pragma unroll
            for (int hh = 0; hh < 2; hh++) {
                int r = rA + hh * 8;
                float sc = g.scale * (g.rowScale ? g.rowScale[(long)z * g.Mrows + r] : 1.f);
                long rowbase = cOff + (long)r * g.ldc;
#pragma unroll
                for (int w = 0; w < 2; w++) {
                    int n = nn + w;
                    float v = c[mt][s][hh * 2 + w] * sc;
                    if (g.bias) v += __ldg(g.bias + n);
                    long idx = rowbase + n;
                    if (g.add) v += g.add[idx];
                    if (g.act == 1) v = fmaxf(v, 0.f);
                    else if (g.act == 2) v = v > 0.f ? v : 0.01f * v;
                    else if (g.act == 3) v = fexp(v);
                    if (g.rsum) lsum[hh] += v;
                    if (g.res) v = g.res[idx] + alpha * v;
                    if (g.Cf) g.Cf[idx] = v;
                    if (g.Cb) {
                        long bi;
                        if (g.perm == 0) bi = idx;
                        else {
                            int bb = r >> 10, l = r & 1023, h = n >> 6, dd = n & 63;
                            long bh = (bb << 4) + h;
                            bi = (g.perm == 1) ? ((bh << 10) + l) * 64 + dd
                                               : ((bh << 6) + dd) * 1024 + l;
                        }
                        g.Cb[bi] = __float2bfloat16(v);
                    }
                }
            }
        }
        if (g.rsum) {
            int rA = m0 + wm * 32 + mt * 16 + (lid >> 2);
#pragma unroll
            for (int hh = 0; hh < 2; hh++) {
                float t = lsum[hh];
                t += __shfl_xor_sync(0xffffffffu, t, 1);
                t += __shfl_xor_sync(0xffffffffu, t, 2);
                if ((lid & 3) == 0)
                    atomicAdd(g.rsum + (long)z * g.Mrows + rA + hh * 8, t);
            }
        }
    }
}

// ---------------- small utility kernels ----------------
__global__ void zero_k(float* __restrict__ p, int n) {
    int i = blockIdx.x * 256 + threadIdx.x;
    if (i < n) p[i] = 0.f;
}
__global__ void recip_k(float* __restrict__ p, int n) {
    int i = blockIdx.x * 256 + threadIdx.x;
    if (i < n) p[i] = 1.0f / p[i];
}

// ---------------- conversions ----------------
__global__ void __launch_bounds__(256) conv_k(const float* __restrict__ s,
                                              __nv_bfloat16* __restrict__ d, long n)
{
    long i = ((long)blockIdx.x * 256 + threadIdx.x) << 2;
    if (i < n) {
        float4 v = *(const float4*)(s + i);
        __nv_bfloat162 lo = __floats2bfloat162_rn(v.x, v.y);
        __nv_bfloat162 hi = __floats2bfloat162_rn(v.z, v.w);
        uint2 u; u.x = *(uint32_t*)&lo; u.y = *(uint32_t*)&hi;
        *(uint2*)(d + i) = u;
    }
}
// strided conv: src [rows,1024] fp32 row-major -> dst bf16 rows with ld=2048
__global__ void __launch_bounds__(256) conv_st_k(const float* __restrict__ s,
                                                 __nv_bfloat16* __restrict__ d, long n)
{
    long i = ((long)blockIdx.x * 256 + threadIdx.x) << 2;
    if (i < n) {
        float4 v = *(const float4*)(s + i);
        __nv_bfloat162 lo = __floats2bfloat162_rn(v.x, v.y);
        __nv_bfloat162 hi = __floats2bfloat162_rn(v.z, v.w);
        uint2 u; u.x = *(uint32_t*)&lo; u.y = *(uint32_t*)&hi;
        long row = i >> 10, col = i & 1023;
        *(uint2*)(d + row * 2048 + col) = u;
    }
}
__global__ void convT_k(const float* __restrict__ s, __nv_bfloat16* __restrict__ d,
                        int R, int C)
{
    __shared__ float t[32][33];
    int c0 = blockIdx.x << 5, r0 = blockIdx.y << 5;
    int x = threadIdx.x, y = threadIdx.y;
#pragma unroll
    for (int i = 0; i < 32; i += 8)
        t[y + i][x] = s[(long)(r0 + y + i) * C + c0 + x];
    __syncthreads();
#pragma unroll
    for (int i = 0; i < 32; i += 8)
        d[(long)(c0 + y + i) * R + r0 + x] = __float2bfloat16(t[x][y + i]);
}
// fused: read tile once -> row-major bf16 copy (d1) AND transposed bf16 (d2)
__global__ void convTB_k(const float* __restrict__ s, __nv_bfloat16* __restrict__ d1,
                         __nv_bfloat16* __restrict__ d2, int R, int C)
{
    __shared__ float t[32][33];
    int c0 = blockIdx.x << 5, r0 = blockIdx.y << 5;
    int x = threadIdx.x, y = threadIdx.y;
#pragma unroll
    for (int i = 0; i < 32; i += 8) {
        float v = s[(long)(r0 + y + i) * C + c0 + x];
        t[y + i][x] = v;
        d1[(long)(r0 + y + i) * C + c0 + x] = __float2bfloat16(v);
    }
    __syncthreads();
#pragma unroll
    for (int i = 0; i < 32; i += 8)
        d2[(long)(c0 + y + i) * R + r0 + x] = __float2bfloat16(t[x][y + i]);
}

// ---------------- host helpers ----------------
static void conv(const float* s, __nv_bfloat16* d, long n, cudaStream_t st = 0) {
    conv_k<<<(unsigned)((n / 4 + 255) / 256), 256, 0, st>>>(s, d, n);
}
static void convT(const float* s, __nv_bfloat16* d, int R, int C, cudaStream_t st = 0) {
    convT_k<<<dim3(C / 32, R / 32), dim3(32, 8), 0, st>>>(s, d, R, C);
}

static void tg(const __nv_bfloat16* A, const __nv_bfloat16* B, float* Cf, __nv_bfloat16* Cb,
               int Mtiles, int Ntot, int K, int lda, int ldb, int ldc, int NT,
               int batch = 1,
               long sAo = 0, long sAi = 0, long sBo = 0, long sBi = 0,
               long sCo = 0, long sCi = 0, int zInner = 1,
               const float* bias = nullptr, const float* add = nullptr,
               const float* res = nullptr, const float* alpha = nullptr,
               const float* rowScale = nullptr, float scale = 1.0f,
               int act = 0, int perm = 0, float* rsum = nullptr,
               cudaStream_t st = 0)
{
    GP g;
    g.A = A; g.B = B; g.Cf = Cf; g.Cb = Cb;
    g.K = K; g.lda = lda; g.ldb = ldb; g.ldc = ldc;
    g.Mrows = Mtiles * 128; g.zInner = zInner; g.act = act; g.perm = perm;
    g.sAo = sAo; g.sAi = sAi; g.sBo = sBo; g.sBi = sBi; g.sCo = sCo; g.sCi = sCi;
    g.bias = bias; g.add = add; g.res = res; g.alpha = alpha; g.rowScale = rowScale;
    g.rsum = rsum; g.scale = scale;
    dim3 grid(Mtiles, Ntot / NT, batch);
    if (NT == 128) {
        static bool done = false;
        if (!done) {
            cudaFuncSetAttribute(tgemm_k<128>,
                                 cudaFuncAttributeMaxDynamicSharedMemorySize, 3 * 32768);
            done = true;
        }
        tgemm_k<128><<<grid, 256, 3 * 32768, st>>>(g);
    } else {
        static bool done = false;
        if (!done) {
            cudaFuncSetAttribute(tgemm_k<64>,
                                 cudaFuncAttributeMaxDynamicSharedMemorySize, 3 * 24576);
            done = true;
        }
        tgemm_k<64><<<grid, 256, 3 * 24576, st>>>(g);
    }
}

extern "C" void kernel_launch(void* const* d_in, const int* in_sizes, int n_in,
                              void* d_out, int out_size)
{
    const float* tgt   = (const float*)d_in[0];
    const float* src   = (const float*)d_in[1];
    const float* emb   = (const float*)d_in[2];
    const float* va_w  = (const float*)d_in[3];
    const float* va_b  = (const float*)d_in[4];
    const float* a_va  = (const float*)d_in[5];
    const float* sa_wq = (const float*)d_in[6];
    const float* sa_bq = (const float*)d_in[7];
    const float* sa_wk = (const float*)d_in[8];
    const float* sa_bk = (const float*)d_in[9];
    const float* sa_wv = (const float*)d_in[10];
    const float* sa_bv = (const float*)d_in[11];
    const float* sa_wo = (const float*)d_in[12];
    const float* sa_bo = (const float*)d_in[13];
    const float* a_sa  = (const float*)d_in[14];
    const float* ca_wq = (const float*)d_in[15];
    const float* ca_bq = (const float*)d_in[16];
    const float* ca_wk = (const float*)d_in[17];
    const float* ca_bk = (const float*)d_in[18];
    const float* ca_wv = (const float*)d_in[19];
    const float* ca_bv = (const float*)d_in[20];
    const float* ca_wo = (const float*)d_in[21];
    const float* ca_bo = (const float*)d_in[22];
    const float* a_ca  = (const float*)d_in[23];
    const float* ff_w1 = (const float*)d_in[24];
    const float* ff_b1 = (const float*)d_in[25];
    const float* ff_w2 = (const float*)d_in[26];
    const float* ff_b2 = (const float*)d_in[27];
    const float* a_ff  = (const float*)d_in[28];
    float* out = (float*)d_out;

    void* p;
    cudaGetSymbolAddress(&p, g_x1);   float* x1   = (float*)p;
    cudaGetSymbolAddress(&p, g_x2);   float* x2   = (float*)p;
    cudaGetSymbolAddress(&p, g_rs);   float* rs   = (float*)p;
    cudaGetSymbolAddress(&p, g_Pb);   __nv_bfloat16* Pb   = (__nv_bfloat16*)p;
    cudaGetSymbolAddress(&p, g_eb);   __nv_bfloat16* eb   = (__nv_bfloat16*)p;
    cudaGetSymbolAddress(&p, g_ebT);  __nv_bfloat16* ebT  = (__nv_bfloat16*)p;
    cudaGetSymbolAddress(&p, g_cat);  __nv_bfloat16* catb = (__nv_bfloat16*)p;
    cudaGetSymbolAddress(&p, g_srcb); __nv_bfloat16* srcb = (__nv_bfloat16*)p;
    cudaGetSymbolAddress(&p, g_x1b);  __nv_bfloat16* x1b  = (__nv_bfloat16*)p;
    cudaGetSymbolAddress(&p, g_x2b);  __nv_bfloat16* x2b  = (__nv_bfloat16*)p;
    cudaGetSymbolAddress(&p, g_qb);   __nv_bfloat16* qb   = (__nv_bfloat16*)p;
    cudaGetSymbolAddress(&p, g_kb);   __nv_bfloat16* kb   = (__nv_bfloat16*)p;
    cudaGetSymbolAddress(&p, g_vtb);  __nv_bfloat16* vtb  = (__nv_bfloat16*)p;
    cudaGetSymbolAddress(&p, g_yb);   __nv_bfloat16* yb   = (__nv_bfloat16*)p;
    cudaGetSymbolAddress(&p, g_hb);   __nv_bfloat16* hb   = (__nv_bfloat16*)p;
    cudaGetSymbolAddress(&p, g_vawT); __nv_bfloat16* vawT = (__nv_bfloat16*)p;
    cudaGetSymbolAddress(&p, g_wT);   __nv_bfloat16* wT   = (__nv_bfloat16*)p;
    cudaGetSymbolAddress(&p, g_f1T);  __nv_bfloat16* f1T  = (__nv_bfloat16*)p;
    cudaGetSymbolAddress(&p, g_f2T);  __nv_bfloat16* f2T  = (__nv_bfloat16*)p;
    const size_t WSZ = (size_t)DMODEL * DMODEL;

    // static side streams + events (capture-legal fork/join)
    static cudaStream_t s1 = nullptr, s2 = nullptr;
    static cudaEvent_t eF, e1, e2;
    if (!s1) {
        cudaStreamCreateWithFlags(&s1, cudaStreamNonBlocking);
        cudaStreamCreateWithFlags(&s2, cudaStreamNonBlocking);
        cudaEventCreateWithFlags(&eF, cudaEventDisableTiming);
        cudaEventCreateWithFlags(&e1, cudaEventDisableTiming);
        cudaEventCreateWithFlags(&e2, cudaEventDisableTiming);
    }

    const float inv_sd = 1.0f / 32.0f;
    const long sQ = 65536, sS = 1048576;

    // ---- fork: weight transposes on s1, concurrent with the big vocab GEMM ----
    cudaEventRecord(eF, 0);
    cudaStreamWaitEvent(s1, eF, 0);
    convT(va_w,  vawT,         2 * DMODEL, DMODEL, s1);
    convT(sa_wq, wT + 0 * WSZ, DMODEL, DMODEL, s1);
    convT(sa_wk, wT + 1 * WSZ, DMODEL, DMODEL, s1);
    convT(sa_wv, wT + 2 * WSZ, DMODEL, DMODEL, s1);
    convT(sa_wo, wT + 3 * WSZ, DMODEL, DMODEL, s1);
    convT(ca_wq, wT + 4 * WSZ, DMODEL, DMODEL, s1);
    convT(ca_wk, wT + 5 * WSZ, DMODEL, DMODEL, s1);
    convT(ca_wv, wT + 6 * WSZ, DMODEL, DMODEL, s1);
    convT(ca_wo, wT + 7 * WSZ, DMODEL, DMODEL, s1);
    convT(ff_w1, f1T, DMODEL, DFF, s1);
    convT(ff_w2, f2T, DFF, DMODEL, s1);
    cudaEventRecord(e1, s1);

    // ---- main stream: conversions + vocab attention ----
    convTB_k<<<dim3(DMODEL / 32, VOCAB / 32), dim3(32, 8)>>>(emb, eb, ebT, VOCAB, DMODEL);
    conv_st_k<<<(unsigned)(MD / 4 / 256), 256>>>(tgt, catb, (long)MD);
    conv(src, srcb, (long)MD);
    zero_k<<<16, 256>>>(rs, 4096);

    tg(catb, eb, nullptr, Pb, 32, VOCAB, DMODEL, 2 * DMODEL, DMODEL, VOCAB, 128,
       1, 0,0,0,0,0,0,1,
       nullptr, nullptr, nullptr, nullptr, nullptr, 1.f, /*exp*/3, 0, rs);
    recip_k<<<16, 256>>>(rs, 4096);
    tg(Pb, ebT, nullptr, catb + DMODEL, 32, DMODEL, VOCAB, VOCAB, VOCAB, 2 * DMODEL, 128,
       1, 0,0,0,0,0,0,1, nullptr, nullptr, nullptr, nullptr, rs);

    cudaStreamWaitEvent(0, e1, 0);   // join: vawT/wT/f*T ready
    tg(catb, vawT, x1, x1b, 32, DMODEL, 2 * DMODEL, 2 * DMODEL, 2 * DMODEL, DMODEL, 128,
       1, 0,0,0,0,0,0,1, va_b, nullptr, tgt, a_va);

    // ===== Self attention (q/k/v on 3 streams) =====
    cudaEventRecord(eF, 0);
    cudaStreamWaitEvent(s1, eF, 0);
    cudaStreamWaitEvent(s2, eF, 0);
    tg(x1b, wT + 0 * WSZ, nullptr, qb, 32, DMODEL, DMODEL, DMODEL, DMODEL, DMODEL, 128,
       1, 0,0,0,0,0,0,1, sa_bq, nullptr, nullptr, nullptr, nullptr, 1.f, 1, 1);
    tg(x1b, wT + 1 * WSZ, nullptr, kb, 32, DMODEL, DMODEL, DMODEL, DMODEL, DMODEL, 128,
       1, 0,0,0,0,0,0,1, sa_bk, nullptr, nullptr, nullptr, nullptr, 1.f, 1, 1, nullptr, s1);
    tg(x1b, wT + 2 * WSZ, nullptr, vtb, 32, DMODEL, DMODEL, DMODEL, DMODEL, DMODEL, 128,
       1, 0,0,0,0,0,0,1, sa_bv, nullptr, nullptr, nullptr, nullptr, 1.f, 1, 2, nullptr, s2);
    zero_k<<<256, 256>>>(rs, 65536);
    cudaEventRecord(e1, s1);
    cudaEventRecord(e2, s2);
    cudaStreamWaitEvent(0, e1, 0);
    cudaStreamWaitEvent(0, e2, 0);

    tg(qb, kb, nullptr, Pb, 8, 1024, 64, 64, 64, 1024, 128,
       64, sQ, 0, sQ, 0, sS, 0, 1,
       nullptr, nullptr, nullptr, nullptr, nullptr, inv_sd, 3, 0, rs);
    recip_k<<<256, 256>>>(rs, 65536);
    tg(Pb, vtb, nullptr, yb, 8, 64, 1024, 1024, 1024, DMODEL, 64,
       64, 16L * sS, sS, 16L * sQ, sQ, (long)1024 * DMODEL, 64, 16,
       nullptr, nullptr, nullptr, nullptr, rs);
    tg(yb, wT + 3 * WSZ, x2, x2b, 32, DMODEL, DMODEL, DMODEL, DMODEL, DMODEL, 128,
       1, 0,0,0,0,0,0,1, sa_bo, nullptr, x1, a_sa, nullptr, 1.f, 1, 0);

    // ===== Cross attention (q/k/v on 3 streams) =====
    cudaEventRecord(eF, 0);
    cudaStreamWaitEvent(s1, eF, 0);
    cudaStreamWaitEvent(s2, eF, 0);
    tg(x2b, wT + 4 * WSZ, nullptr, qb, 32, DMODEL, DMODEL, DMODEL, DMODEL, DMODEL, 128,
       1, 0,0,0,0,0,0,1, ca_bq, nullptr, nullptr, nullptr, nullptr, 1.f, 1, 1);
    tg(srcb, wT + 5 * WSZ, nullptr, kb, 32, DMODEL, DMODEL, DMODEL, DMODEL, DMODEL, 128,
       1, 0,0,0,0,0,0,1, ca_bk, nullptr, nullptr, nullptr, nullptr, 1.f, 1, 1, nullptr, s1);
    tg(srcb, wT + 6 * WSZ, nullptr, vtb, 32, DMODEL, DMODEL, DMODEL, DMODEL, DMODEL, 128,
       1, 0,0,0,0,0,0,1, ca_bv, nullptr, nullptr, nullptr, nullptr, 1.f, 1, 2, nullptr, s2);
    zero_k<<<256, 256>>>(rs, 65536);
    cudaEventRecord(e1, s1);
    cudaEventRecord(e2, s2);
    cudaStreamWaitEvent(0, e1, 0);
    cudaStreamWaitEvent(0, e2, 0);

    tg(qb, kb, nullptr, Pb, 8, 1024, 64, 64, 64, 1024, 128,
       64, sQ, 0, sQ, 0, sS, 0, 1,
       nullptr, nullptr, nullptr, nullptr, nullptr, inv_sd, 3, 0, rs);
    recip_k<<<256, 256>>>(rs, 65536);
    tg(Pb, vtb, nullptr, yb, 8, 64, 1024, 1024, 1024, DMODEL, 64,
       64, 16L * sS, sS, 16L * sQ, sQ, (long)1024 * DMODEL, 64, 16,
       nullptr, nullptr, nullptr, nullptr, rs);
    tg(yb, wT + 7 * WSZ, x1, x1b, 32, DMODEL, DMODEL, DMODEL, DMODEL, DMODEL, 128,
       1, 0,0,0,0,0,0,1, ca_bo, nullptr, x2, a_ca, nullptr, 1.f, 1, 0);

    // ===== Feed forward =====
    tg(x1b, f1T, nullptr, hb, 32, DFF, DMODEL, DMODEL, DMODEL, DFF, 128,
       1, 0,0,0,0,0,0,1, ff_b1, nullptr, nullptr, nullptr, nullptr, 1.f, 2, 0);
    tg(hb, f2T, out, nullptr, 32, DMODEL, DFF, DFF, DFF, DMODEL, 128,
       1, 0,0,0,0,0,0,1, ff_b2, nullptr, x1, a_ff, nullptr, 1.f, 0, 0);
}